// round 7
// baseline (speedup 1.0000x reference)
#include <cuda_runtime.h>
#include <cstdint>

#define N_NODES 100000
#define CAP 64          // per-node bucket capacity; P(Poisson(16) > 64) ~ 1e-20
#define CHUNK 8         // edges staged per pipeline step
#define WPB 8           // warps per block

// Scratch (device globals — no runtime allocation allowed).
__device__ int  g_cursor[N_NODES];                  // doubles as in-degree
__device__ int2 g_slot[(size_t)N_NODES * CAP];      // (src, edge_id), 51.2 MB

// ---------------------------------------------------------------------------
// Kernel 1: bucket fill. One thread per edge.
// ---------------------------------------------------------------------------
__global__ void __launch_bounds__(256)
fill_kernel(const int* __restrict__ src, const int* __restrict__ dst, int n_edges)
{
    int e = blockIdx.x * blockDim.x + threadIdx.x;
    if (e >= n_edges) return;
    int s = __ldg(&src[e]);
    int d = __ldg(&dst[e]);
    int pos = atomicAdd(&g_cursor[d], 1);
    if (pos < CAP)
        g_slot[(size_t)d * CAP + pos] = make_int2(s, e);
}

// ---------------------------------------------------------------------------
// Kernel 2: gather, warp-per-node, cp.async double-buffered smem staging.
//   lane = sub*8 + feat. Slots preloaded to registers once; chunk c+1 streams
//   into smem via LDGSTS while chunk c is consumed -> loads stay outstanding
//   through the consume phase (raise DRAM duty cycle).
// ---------------------------------------------------------------------------
__global__ void __launch_bounds__(256)
gather_kernel(const float4* __restrict__ rel,      // [N, 8] float4
              const float4* __restrict__ pat,      // [E, 8] float4
              float4* __restrict__ out)            // [N, 8] float4
{
    // per warp: [buf:2][arr:2 (0=pat,1=rel)][edge:CHUNK][piece:8] float4 = 4KB
    __shared__ float4 stage[WPB * 2 * 2 * CHUNK * 8];   // 32 KB

    int warp = threadIdx.x >> 5;
    int node = blockIdx.x * WPB + warp;
    if (node >= N_NODES) return;
    int lane = threadIdx.x & 31;
    int sub  = lane >> 3;          // 0..3
    int feat = lane & 7;           // 0..7

    int deg = g_cursor[node];
    int n = min(deg, CAP);
    const int2* slots = &g_slot[(size_t)node * CAP];

    float4* ws = &stage[warp * (2 * 2 * CHUNK * 8)];

    float4 acc = make_float4(0.f, 0.f, 0.f, 0.f);

    if (n > 0) {
        // Preload all slots once: lane holds entries lane and lane+32.
        int2 s01 = __ldg(&slots[min(lane,      n - 1)]);
        int2 s23 = __ldg(&slots[min(32 + lane, n - 1)]);

        int nchunks = (n + CHUNK - 1) / CHUNK;

        auto stage_chunk = [&](int c, int buf) {
#pragma unroll
            for (int r = 0; r < 2; r++) {
                int e_loc = r * 4 + sub;               // 0..7 across lanes
                int i = c * CHUNK + e_loc;
                int ic = (i < n) ? i : 0;              // clamp: slot 0 is valid
                int srcl = ic & 31;
                int eA = __shfl_sync(0xFFFFFFFFu, s01.y, srcl);
                int eB = __shfl_sync(0xFFFFFFFFu, s23.y, srcl);
                int sA = __shfl_sync(0xFFFFFFFFu, s01.x, srcl);
                int sB = __shfl_sync(0xFFFFFFFFu, s23.x, srcl);
                int eid = (ic < 32) ? eA : eB;
                int sid = (ic < 32) ? sA : sB;
                const float4* psrc = &pat[(size_t)eid * 8 + feat];
                const float4* rsrc = &rel[(size_t)sid * 8 + feat];
                float4* pdst = ws + ((buf * 2 + 0) * CHUNK + e_loc) * 8 + feat;
                float4* rdst = ws + ((buf * 2 + 1) * CHUNK + e_loc) * 8 + feat;
                unsigned pd = (unsigned)__cvta_generic_to_shared(pdst);
                unsigned rd = (unsigned)__cvta_generic_to_shared(rdst);
                asm volatile("cp.async.cg.shared.global [%0], [%1], 16;\n"
                             :: "r"(pd), "l"(psrc));
                asm volatile("cp.async.cg.shared.global [%0], [%1], 16;\n"
                             :: "r"(rd), "l"(rsrc));
            }
            asm volatile("cp.async.commit_group;\n");
        };

        stage_chunk(0, 0);
        for (int c = 0; c < nchunks; c++) {
            int buf = c & 1;
            if (c + 1 < nchunks) {
                stage_chunk(c + 1, buf ^ 1);
                asm volatile("cp.async.wait_group 1;\n");   // chunk c complete
            } else {
                asm volatile("cp.async.wait_group 0;\n");
            }
            __syncwarp();
#pragma unroll
            for (int k = 0; k < 2; k++) {
                int e_loc = k * 4 + sub;
                int i = c * CHUNK + e_loc;
                if (i < n) {
                    float4 p = ws[((buf * 2 + 0) * CHUNK + e_loc) * 8 + feat];
                    float4 r = ws[((buf * 2 + 1) * CHUNK + e_loc) * 8 + feat];
                    acc.x = fmaf(r.x, p.x, acc.x);
                    acc.y = fmaf(r.y, p.y, acc.y);
                    acc.z = fmaf(r.z, p.z, acc.z);
                    acc.w = fmaf(r.w, p.w, acc.w);
                }
            }
            __syncwarp();   // all lanes done reading buf before it is restaged
        }

        // Fold the 4 sub-accumulators (lanes 8 apart share feat).
        acc.x += __shfl_xor_sync(0xFFFFFFFFu, acc.x, 8);
        acc.y += __shfl_xor_sync(0xFFFFFFFFu, acc.y, 8);
        acc.z += __shfl_xor_sync(0xFFFFFFFFu, acc.z, 8);
        acc.w += __shfl_xor_sync(0xFFFFFFFFu, acc.w, 8);
        acc.x += __shfl_xor_sync(0xFFFFFFFFu, acc.x, 16);
        acc.y += __shfl_xor_sync(0xFFFFFFFFu, acc.y, 16);
        acc.z += __shfl_xor_sync(0xFFFFFFFFu, acc.z, 16);
        acc.w += __shfl_xor_sync(0xFFFFFFFFu, acc.w, 16);
    }

    if (sub == 0) {
        float inv = 1.0f / fmaxf((float)deg, 1.0f);
        float4 rl = __ldg(&rel[(size_t)node * 8 + feat]);
        float4 o;
        o.x = fmaf(acc.x, inv, rl.x);
        o.y = fmaf(acc.y, inv, rl.y);
        o.z = fmaf(acc.z, inv, rl.z);
        o.w = fmaf(acc.w, inv, rl.w);
        out[(size_t)node * 8 + feat] = o;
    }
}

// ---------------------------------------------------------------------------
extern "C" void kernel_launch(void* const* d_in, const int* in_sizes, int n_in,
                              void* d_out, int out_size)
{
    const float4* rel = (const float4*)d_in[0];     // [N, 32] f32
    const float4* pat = (const float4*)d_in[1];     // [E, 32] f32
    const int*    src = (const int*)d_in[2];        // [E] int32
    const int*    dst = (const int*)d_in[3];        // [E] int32
    float4* out = (float4*)d_out;

    const int n_edges = in_sizes[2];                // 1,600,000

    // 1) zero bucket cursors via async memset (graph-capturable)
    void* cursor_ptr = nullptr;
    cudaGetSymbolAddress(&cursor_ptr, g_cursor);
    cudaMemsetAsync(cursor_ptr, 0, N_NODES * sizeof(int));

    // 2) bucket fill: one thread per edge
    fill_kernel<<<(n_edges + 255) / 256, 256>>>(src, dst, n_edges);

    // 3) gather: one warp per node, cp.async pipelined
    gather_kernel<<<(N_NODES + WPB - 1) / WPB, 256>>>(rel, pat, out);
}